// round 8
// baseline (speedup 1.0000x reference)
#include <cuda_runtime.h>
#include <math.h>

// ---------------------------------------------------------------------------
// GCNClassifier: 3x GCNConv (+leaky relu) + linear + log_softmax
// N = 100000, E = 1000000, dims 64 -> 80 -> 40 -> 50 -> 10
// Strategy: per-call CSR build (by dst), warp-per-node gather aggregation
// (coalesced, divergence-free, no float atomics), register-tiled fused GEMMs
// with f32x2 FMAs. Layer 1 aggregates BEFORE its GEMM; final head fused into
// the layer-3 aggregation.
// ---------------------------------------------------------------------------

#define N_NODES 100000
#define E_MAX   1000000
#define MAX_DIM 80
#define SCAN_B  1024
#define NB_MAX  128   // cdiv(100000,1024)=98

__device__ float g_bufA[N_NODES * MAX_DIM];
__device__ float g_bufB[N_NODES * MAX_DIM];
__device__ float g_bufC[N_NODES * MAX_DIM];
__device__ float g_dinv[N_NODES];
__device__ int   g_deg[N_NODES];
__device__ int   g_incl[N_NODES];
__device__ int   g_bsum[NB_MAX];
__device__ int   g_off[N_NODES + 1];
__device__ int   g_cur[N_NODES];
__device__ int   g_csrc[E_MAX];

static inline int cdiv(int a, int b) { return (a + b - 1) / b; }

// ---------------------------------------------------------------------------
// CSR build: histogram -> scan (+dinv) -> offsets (inline bsum scan) -> scatter
// ---------------------------------------------------------------------------
__global__ void deg_zero(int* deg, int n) {
    int i = blockIdx.x * blockDim.x + threadIdx.x;
    if (i < n) deg[i] = 0;
}

__global__ void deg_hist(const int* __restrict__ dst, int* deg, int E) {
    int e = blockIdx.x * blockDim.x + threadIdx.x;
    if (e < E) atomicAdd(&deg[__ldg(&dst[e])], 1);
}

__global__ void scan_block(const int* __restrict__ deg, int* incl, int* bsum,
                           float* dinv, int n) {
    __shared__ int sh[SCAN_B];
    int i = blockIdx.x * SCAN_B + threadIdx.x;
    int d = (i < n) ? deg[i] : 0;
    sh[threadIdx.x] = d;
    if (i < n) dinv[i] = rsqrtf((float)d + 1.0f);
    __syncthreads();
#pragma unroll
    for (int ofs = 1; ofs < SCAN_B; ofs <<= 1) {
        int t = (threadIdx.x >= ofs) ? sh[threadIdx.x - ofs] : 0;
        __syncthreads();
        sh[threadIdx.x] += t;
        __syncthreads();
    }
    if (i < n) incl[i] = sh[threadIdx.x];
    if (threadIdx.x == SCAN_B - 1) bsum[blockIdx.x] = sh[SCAN_B - 1];
}

// blockDim must be 256: each block's 256 indices share one scan-block (>>10).
__global__ void finish_offsets(const int* __restrict__ deg,
                               const int* __restrict__ incl,
                               const int* __restrict__ bsum,
                               int* off, int* cur, int n, int E) {
    __shared__ int red[256];
    const int sb = blockIdx.x >> 2;  // scan-block index for this whole block
    int partial = 0;
    for (int i = threadIdx.x; i < sb; i += 256) partial += __ldg(&bsum[i]);
    red[threadIdx.x] = partial;
    __syncthreads();
#pragma unroll
    for (int o = 128; o > 0; o >>= 1) {
        if (threadIdx.x < o) red[threadIdx.x] += red[threadIdx.x + o];
        __syncthreads();
    }
    const int boff = red[0];
    int i = blockIdx.x * 256 + threadIdx.x;
    if (i < n) {
        int o = incl[i] - deg[i] + boff;
        off[i] = o;
        cur[i] = o;
        if (i == 0) off[n] = E;
    }
}

__global__ void csr_scatter(const int* __restrict__ src,
                            const int* __restrict__ dst,
                            int* cur, int* csrc, int E) {
    int e = blockIdx.x * blockDim.x + threadIdx.x;
    if (e < E) {
        int d = __ldg(&dst[e]);
        int pos = atomicAdd(&cur[d], 1);
        csrc[pos] = __ldg(&src[e]);
    }
}

// ---------------------------------------------------------------------------
// Layer-1 warp-per-node aggregate on x (dim 64):
//   Z[i] = dinv[i]*(sum_s dinv[s]*x[s]) + dinv[i]^2 * x[i]
// ---------------------------------------------------------------------------
__global__ void agg_x_warp(const float* __restrict__ X,
                           const int* __restrict__ off,
                           const int* __restrict__ csrc,
                           const float* __restrict__ dinv,
                           float* __restrict__ Z, int n) {
    const int gw = (blockIdx.x * blockDim.x + threadIdx.x) >> 5;
    const int lane = threadIdx.x & 31;
    if (gw >= n) return;
    const int e0 = __ldg(&off[gw]);
    const int e1 = __ldg(&off[gw + 1]);
    float s0 = 0.f, s1 = 0.f;
    for (int base = e0; base < e1; base += 32) {
        const int m = min(32, e1 - base);
        int idx = 0; float dv = 0.f;
        if (base + lane < e1) {
            idx = __ldg(&csrc[base + lane]);
            dv = __ldg(&dinv[idx]);
        }
        for (int j = 0; j < m; j++) {
            const int s = __shfl_sync(0xffffffffu, idx, j);
            const float d = __shfl_sync(0xffffffffu, dv, j);
            const float* row = X + (size_t)s * 64;
            s0 = fmaf(__ldg(&row[lane]), d, s0);
            s1 = fmaf(__ldg(&row[lane + 32]), d, s1);
        }
    }
    const float di = __ldg(&dinv[gw]);
    const float di2 = di * di;
    const float* xr = X + (size_t)gw * 64;
    float* zr = Z + (size_t)gw * 64;
    zr[lane]      = fmaf(s0, di, __ldg(&xr[lane]) * di2);
    zr[lane + 32] = fmaf(s1, di, __ldg(&xr[lane + 32]) * di2);
}

// ---------------------------------------------------------------------------
// Warp-per-node gather (agg-after layers):
//   AGG[node] += (sum over incoming src of Hs[src]) * dinv[node]
// AGG pre-holds self-loop + bias (from GEMM epilogue).
// ---------------------------------------------------------------------------
template <int DIM>
__global__ void agg_h_warp(const float* __restrict__ Hs,
                           const int* __restrict__ off,
                           const int* __restrict__ csrc,
                           const float* __restrict__ dinv,
                           float* __restrict__ AGG, int n) {
    constexpr int NR = (DIM + 31) / 32;
    const int gw = (blockIdx.x * blockDim.x + threadIdx.x) >> 5;
    const int lane = threadIdx.x & 31;
    if (gw >= n) return;
    const int e0 = __ldg(&off[gw]);
    const int e1 = __ldg(&off[gw + 1]);
    float sum[NR];
#pragma unroll
    for (int r = 0; r < NR; r++) sum[r] = 0.f;
    for (int base = e0; base < e1; base += 32) {
        const int m = min(32, e1 - base);
        int idx = 0;
        if (base + lane < e1) idx = __ldg(&csrc[base + lane]);
        for (int j = 0; j < m; j++) {
            const int s = __shfl_sync(0xffffffffu, idx, j);
            const float* row = Hs + (size_t)s * DIM;
#pragma unroll
            for (int r = 0; r < NR; r++) {
                int c = lane + r * 32;
                if (c < DIM) sum[r] += __ldg(&row[c]);
            }
        }
    }
    const float nd = __ldg(&dinv[gw]);
    float* ag = AGG + (size_t)gw * DIM;
#pragma unroll
    for (int r = 0; r < NR; r++) {
        int c = lane + r * 32;
        if (c < DIM) ag[c] = fmaf(sum[r], nd, ag[c]);
    }
}

// ---------------------------------------------------------------------------
// Layer-3 aggregation (dim 50) fused with final head:
//   h3 = AGG + gathered*dinv; v = leaky(h3); logits = v @ Wl + bl; log_softmax
// Warp per node; 10 lanes compute logits from an smem-transposed row.
// ---------------------------------------------------------------------------
__global__ __launch_bounds__(256)
void agg3_final(const float* __restrict__ Hs,
                const int* __restrict__ off,
                const int* __restrict__ csrc,
                const float* __restrict__ dinv,
                const float* __restrict__ AGG,
                const float* __restrict__ Wl,
                const float* __restrict__ bl,
                float* __restrict__ out, int n) {
    constexpr int DIM = 50;
    __shared__ float Ws[500];
    __shared__ float bs[10];
    __shared__ float vrow[8][DIM + 2];

    for (int i = threadIdx.x; i < 500; i += 256) Ws[i] = Wl[i];
    if (threadIdx.x < 10) bs[threadIdx.x] = bl[threadIdx.x];
    __syncthreads();

    const int gw = (blockIdx.x * blockDim.x + threadIdx.x) >> 5;
    const int lane = threadIdx.x & 31;
    const int w = threadIdx.x >> 5;
    if (gw >= n) return;

    const int e0 = __ldg(&off[gw]);
    const int e1 = __ldg(&off[gw + 1]);
    float s0 = 0.f, s1 = 0.f;
    const int c1 = lane + 32;
    for (int base = e0; base < e1; base += 32) {
        const int m = min(32, e1 - base);
        int idx = 0;
        if (base + lane < e1) idx = __ldg(&csrc[base + lane]);
        for (int j = 0; j < m; j++) {
            const int s = __shfl_sync(0xffffffffu, idx, j);
            const float* row = Hs + (size_t)s * DIM;
            s0 += __ldg(&row[lane]);
            if (c1 < DIM) s1 += __ldg(&row[c1]);
        }
    }
    const float nd = __ldg(&dinv[gw]);
    const float* ag = AGG + (size_t)gw * DIM;
    float v0 = fmaf(s0, nd, __ldg(&ag[lane]));
    v0 = (v0 > 0.f) ? v0 : 0.01f * v0;
    vrow[w][lane] = v0;
    if (c1 < DIM) {
        float v1 = fmaf(s1, nd, __ldg(&ag[c1]));
        v1 = (v1 > 0.f) ? v1 : 0.01f * v1;
        vrow[w][c1] = v1;
    }
    __syncwarp();

    float logit = -INFINITY;
    if (lane < 10) {
        logit = bs[lane];
#pragma unroll
        for (int k = 0; k < DIM; k++)
            logit = fmaf(vrow[w][k], Ws[k * 10 + lane], logit);
    }
    // warp-wide max / sum-exp reductions (inactive lanes: -inf / 0)
    float mx = logit;
#pragma unroll
    for (int o = 16; o > 0; o >>= 1)
        mx = fmaxf(mx, __shfl_xor_sync(0xffffffffu, mx, o));
    float ex = (lane < 10) ? __expf(logit - mx) : 0.f;
#pragma unroll
    for (int o = 16; o > 0; o >>= 1)
        ex += __shfl_xor_sync(0xffffffffu, ex, o);
    const float lse = mx + __logf(ex);
    if (lane < 10) out[(size_t)gw * 10 + lane] = logit - lse;
}

// ---------------------------------------------------------------------------
// Register-tiled fused GEMM.
//   acc = leaky?(X[rows]) @ W       TM x TN tile per thread, f32x2 FMAs
// GCNEPI=true:  Hs = acc*dinv, AGG = acc*dinv^2 + b   (agg-after layers)
// GCNEPI=false: OUT(=AGG param) = acc + b             (plain)
// X and outputs must not alias.
// ---------------------------------------------------------------------------
template <int K, int DOUT, int BM, int BK, int TM, int TN, int THREADS,
          bool LEAKY, bool GCNEPI>
__global__ __launch_bounds__(THREADS)
void gemm_fused(const float* __restrict__ X,
                const float* __restrict__ W,
                const float* __restrict__ b,
                const float* __restrict__ dinv,
                float* __restrict__ Hs,
                float* __restrict__ AGG, int n) {
    constexpr int COLG = DOUT / TN;
    constexpr int ROWG = THREADS / COLG;
    constexpr int NP = TN / 2;
    static_assert(COLG * TN == DOUT, "tn");
    static_assert(COLG * ROWG == THREADS, "thr");
    static_assert(ROWG * TM == BM, "bm");
    static_assert(K % BK == 0, "bk");

    __shared__ __align__(16) float Ws[K * DOUT];
    __shared__ __align__(16) float Xs[BM * (BK + 1)];

    const int tid = threadIdx.x;
    const int row0 = blockIdx.x * BM;
    const int nrows = min(BM, n - row0);

    for (int i = tid; i < K * DOUT; i += THREADS) Ws[i] = W[i];

    const int colg = tid % COLG;
    const int rowg = tid / COLG;
    const int col0 = colg * TN;
    const int r0 = rowg * TM;

    unsigned long long acc[TM][NP];
#pragma unroll
    for (int i = 0; i < TM; i++)
#pragma unroll
        for (int jp = 0; jp < NP; jp++) acc[i][jp] = 0ULL;

    for (int k0 = 0; k0 < K; k0 += BK) {
        __syncthreads();
        for (int i = tid; i < nrows * BK; i += THREADS) {
            int r = i / BK, c = i - r * BK;
            float v = __ldg(&X[(size_t)(row0 + r) * K + k0 + c]);
            if (LEAKY) v = (v > 0.0f) ? v : 0.01f * v;
            Xs[r * (BK + 1) + c] = v;
        }
        __syncthreads();

#pragma unroll 4
        for (int k = 0; k < BK; k++) {
            unsigned long long wv[NP];
            const unsigned long long* wr =
                (const unsigned long long*)&Ws[(k0 + k) * DOUT + col0];
#pragma unroll
            for (int jp = 0; jp < NP; jp++) wv[jp] = wr[jp];
#pragma unroll
            for (int i = 0; i < TM; i++) {
                float xv = Xs[(r0 + i) * (BK + 1) + k];
                unsigned long long xp;
                asm("mov.b64 %0, {%1, %1};" : "=l"(xp) : "f"(xv));
#pragma unroll
                for (int jp = 0; jp < NP; jp++) {
                    asm("fma.rn.f32x2 %0, %1, %2, %0;"
                        : "+l"(acc[i][jp]) : "l"(xp), "l"(wv[jp]));
                }
            }
        }
    }

#pragma unroll
    for (int i = 0; i < TM; i++) {
        int row = row0 + r0 + i;
        if (row >= n) break;
        if (GCNEPI) {
            float di = dinv[row];
            float di2 = di * di;
            float2* hsr = (float2*)(Hs + (size_t)row * DOUT + col0);
            float2* agr = (float2*)(AGG + (size_t)row * DOUT + col0);
#pragma unroll
            for (int jp = 0; jp < NP; jp++) {
                float lo, hi;
                asm("mov.b64 {%0, %1}, %2;" : "=f"(lo), "=f"(hi) : "l"(acc[i][jp]));
                float blo = __ldg(&b[col0 + 2 * jp]);
                float bhi = __ldg(&b[col0 + 2 * jp + 1]);
                hsr[jp] = make_float2(lo * di, hi * di);
                agr[jp] = make_float2(lo * di2 + blo, hi * di2 + bhi);
            }
        } else {
            float2* outr = (float2*)(AGG + (size_t)row * DOUT + col0);
#pragma unroll
            for (int jp = 0; jp < NP; jp++) {
                float lo, hi;
                asm("mov.b64 {%0, %1}, %2;" : "=f"(lo), "=f"(hi) : "l"(acc[i][jp]));
                float blo = __ldg(&b[col0 + 2 * jp]);
                float bhi = __ldg(&b[col0 + 2 * jp + 1]);
                outr[jp] = make_float2(lo + blo, hi + bhi);
            }
        }
    }
}

// ---------------------------------------------------------------------------
// launch
// ---------------------------------------------------------------------------
extern "C" void kernel_launch(void* const* d_in, const int* in_sizes, int n_in,
                              void* d_out, int out_size) {
    const float* x = (const float*)d_in[0];
    const int* edge = (const int*)d_in[1];  // int32 (JAX downcast)
    const float* W1 = (const float*)d_in[2];
    const float* b1 = (const float*)d_in[3];
    const float* W2 = (const float*)d_in[4];
    const float* b2 = (const float*)d_in[5];
    const float* W3 = (const float*)d_in[6];
    const float* b3 = (const float*)d_in[7];
    const float* Wl = (const float*)d_in[8];
    const float* bl = (const float*)d_in[9];
    float* out = (float*)d_out;

    const int n = in_sizes[0] / 64;  // 100000
    const int E = in_sizes[1] / 2;   // 1000000
    const int* src = edge;
    const int* dst = edge + E;

    float *bufA, *bufB, *bufC, *dinv;
    int *deg, *incl, *bsum, *off, *cur, *csrc;
    cudaGetSymbolAddress((void**)&bufA, g_bufA);
    cudaGetSymbolAddress((void**)&bufB, g_bufB);
    cudaGetSymbolAddress((void**)&bufC, g_bufC);
    cudaGetSymbolAddress((void**)&dinv, g_dinv);
    cudaGetSymbolAddress((void**)&deg, g_deg);
    cudaGetSymbolAddress((void**)&incl, g_incl);
    cudaGetSymbolAddress((void**)&bsum, g_bsum);
    cudaGetSymbolAddress((void**)&off, g_off);
    cudaGetSymbolAddress((void**)&cur, g_cur);
    cudaGetSymbolAddress((void**)&csrc, g_csrc);

    const int T = 256;
    const int nb = cdiv(n, SCAN_B);
    const int warpGrid = cdiv(n, 8);  // 8 warps per 256-thread block

    // ---- CSR build (by dst) + dinv ----
    deg_zero<<<cdiv(n, T), T>>>(deg, n);
    deg_hist<<<cdiv(E, T), T>>>(dst, deg, E);
    scan_block<<<nb, SCAN_B>>>(deg, incl, bsum, dinv, n);
    finish_offsets<<<cdiv(n, 256), 256>>>(deg, incl, bsum, off, cur, n, E);
    csr_scatter<<<cdiv(E, T), T>>>(src, dst, cur, csrc, E);

    // ---- layer 1: aggregate-first on x (dim 64), then GEMM 64->80 ----
    agg_x_warp<<<warpGrid, T>>>(x, off, csrc, dinv, bufB, n);
    gemm_fused<64, 80, 128, 32, 4, 10, 256, false, false>
        <<<cdiv(n, 128), 256>>>(bufB, W1, b1, dinv, bufA, bufC, n);

    // ---- layer 2: 80 -> 40, agg-after ----  X=bufC(leaky), Hs=bufA, AGG=bufB
    gemm_fused<80, 40, 256, 20, 4, 10, 256, true, true>
        <<<cdiv(n, 256), 256>>>(bufC, W2, b2, dinv, bufA, bufB, n);
    agg_h_warp<40><<<warpGrid, T>>>(bufA, off, csrc, dinv, bufB, n);

    // ---- layer 3: 40 -> 50 ----  X=bufB(leaky), Hs=bufA, AGG=bufC
    gemm_fused<40, 50, 256, 20, 4, 10, 320, true, true>
        <<<cdiv(n, 256), 320>>>(bufB, W3, b3, dinv, bufA, bufC, n);

    // ---- layer-3 aggregation fused with final linear + log_softmax ----
    agg3_final<<<warpGrid, T>>>(bufA, off, csrc, dinv, bufC, Wl, bl, out, n);
}

// round 9
// speedup vs baseline: 1.1460x; 1.1460x over previous
#include <cuda_runtime.h>
#include <math.h>

// ---------------------------------------------------------------------------
// GCNClassifier: 3x GCNConv (+leaky relu) + linear + log_softmax
// N = 100000, E = 1000000, dims 64 -> 80 -> 40 -> 50 -> 10
// Strategy: per-call CSR build (by dst), thread-per-(node,group) vectorized
// gather aggregation (no float atomics), register-tiled fused GEMMs with
// f32x2 FMAs. Layer 1 aggregates BEFORE its GEMM.
// ---------------------------------------------------------------------------

#define N_NODES 100000
#define E_MAX   1000000
#define MAX_DIM 80
#define SCAN_B  1024

__device__ float g_bufA[N_NODES * MAX_DIM];
__device__ float g_bufB[N_NODES * MAX_DIM];
__device__ float g_bufC[N_NODES * MAX_DIM];
__device__ float g_dinv[N_NODES];
__device__ int   g_deg[N_NODES];
__device__ int   g_incl[N_NODES];
__device__ int   g_bsum[128];
__device__ int   g_off[N_NODES + 1];
__device__ int   g_cur[N_NODES];
__device__ int   g_csrc[E_MAX];

static inline int cdiv(int a, int b) { return (a + b - 1) / b; }

// ---------------------------------------------------------------------------
// CSR build: histogram -> scan (+dinv) -> offsets (inline bsum scan) -> scatter
// ---------------------------------------------------------------------------
__global__ void deg_zero(int* deg, int n) {
    int i = blockIdx.x * blockDim.x + threadIdx.x;
    if (i < n) deg[i] = 0;
}

__global__ void deg_hist(const int* __restrict__ dst, int* deg, int E) {
    int e = blockIdx.x * blockDim.x + threadIdx.x;
    if (e < E) atomicAdd(&deg[__ldg(&dst[e])], 1);
}

__global__ void scan_block(const int* __restrict__ deg, int* incl, int* bsum,
                           float* dinv, int n) {
    __shared__ int sh[SCAN_B];
    int i = blockIdx.x * SCAN_B + threadIdx.x;
    int d = (i < n) ? deg[i] : 0;
    sh[threadIdx.x] = d;
    if (i < n) dinv[i] = rsqrtf((float)d + 1.0f);
    __syncthreads();
#pragma unroll
    for (int ofs = 1; ofs < SCAN_B; ofs <<= 1) {
        int t = (threadIdx.x >= ofs) ? sh[threadIdx.x - ofs] : 0;
        __syncthreads();
        sh[threadIdx.x] += t;
        __syncthreads();
    }
    if (i < n) incl[i] = sh[threadIdx.x];
    if (threadIdx.x == SCAN_B - 1) bsum[blockIdx.x] = sh[SCAN_B - 1];
}

// blockDim must be 256: each block's 256 indices share one scan-block (>>10).
__global__ void finish_offsets(const int* __restrict__ deg,
                               const int* __restrict__ incl,
                               const int* __restrict__ bsum,
                               int* off, int* cur, int n, int E) {
    __shared__ int red[256];
    const int sb = blockIdx.x >> 2;  // scan-block index for this whole block
    int partial = 0;
    for (int i = threadIdx.x; i < sb; i += 256) partial += __ldg(&bsum[i]);
    red[threadIdx.x] = partial;
    __syncthreads();
#pragma unroll
    for (int o = 128; o > 0; o >>= 1) {
        if (threadIdx.x < o) red[threadIdx.x] += red[threadIdx.x + o];
        __syncthreads();
    }
    const int boff = red[0];
    int i = blockIdx.x * 256 + threadIdx.x;
    if (i < n) {
        int o = incl[i] - deg[i] + boff;
        off[i] = o;
        cur[i] = o;
        if (i == 0) off[n] = E;
    }
}

__global__ void csr_scatter(const int* __restrict__ src,
                            const int* __restrict__ dst,
                            int* cur, int* csrc, int E) {
    int e = blockIdx.x * blockDim.x + threadIdx.x;
    if (e < E) {
        int d = __ldg(&dst[e]);
        int pos = atomicAdd(&cur[d], 1);
        csrc[pos] = __ldg(&src[e]);
    }
}

// ---------------------------------------------------------------------------
// Layer-1 aggregate-first: Z[i] = dinv[i]*(sum_s dinv[s]*x[s]) + dinv[i]^2*x[i]
// one thread per (node, float4 group), NV = 64/4 = 16; 4-way edge unroll.
// ---------------------------------------------------------------------------
__global__ void agg_x_v4(const float4* __restrict__ X4,
                         const int* __restrict__ off,
                         const int* __restrict__ csrc,
                         const float* __restrict__ dinv,
                         float4* __restrict__ Z, int n) {
    constexpr int NV = 16;
    int idx = blockIdx.x * blockDim.x + threadIdx.x;
    if (idx >= n * NV) return;
    int node = idx / NV;
    int g = idx - node * NV;
    int e = __ldg(&off[node]);
    int e1 = __ldg(&off[node + 1]);
    float4 sum = make_float4(0.f, 0.f, 0.f, 0.f);
    for (; e + 3 < e1; e += 4) {
        int s0 = __ldg(&csrc[e]);
        int s1 = __ldg(&csrc[e + 1]);
        int s2 = __ldg(&csrc[e + 2]);
        int s3 = __ldg(&csrc[e + 3]);
        float d0 = __ldg(&dinv[s0]);
        float d1 = __ldg(&dinv[s1]);
        float d2 = __ldg(&dinv[s2]);
        float d3 = __ldg(&dinv[s3]);
        float4 h0 = __ldg(&X4[(size_t)s0 * NV + g]);
        float4 h1 = __ldg(&X4[(size_t)s1 * NV + g]);
        float4 h2 = __ldg(&X4[(size_t)s2 * NV + g]);
        float4 h3 = __ldg(&X4[(size_t)s3 * NV + g]);
        sum.x = fmaf(h0.x, d0, fmaf(h1.x, d1, fmaf(h2.x, d2, fmaf(h3.x, d3, sum.x))));
        sum.y = fmaf(h0.y, d0, fmaf(h1.y, d1, fmaf(h2.y, d2, fmaf(h3.y, d3, sum.y))));
        sum.z = fmaf(h0.z, d0, fmaf(h1.z, d1, fmaf(h2.z, d2, fmaf(h3.z, d3, sum.z))));
        sum.w = fmaf(h0.w, d0, fmaf(h1.w, d1, fmaf(h2.w, d2, fmaf(h3.w, d3, sum.w))));
    }
    for (; e < e1; e++) {
        int s0 = __ldg(&csrc[e]);
        float d0 = __ldg(&dinv[s0]);
        float4 h0 = __ldg(&X4[(size_t)s0 * NV + g]);
        sum.x = fmaf(h0.x, d0, sum.x);
        sum.y = fmaf(h0.y, d0, sum.y);
        sum.z = fmaf(h0.z, d0, sum.z);
        sum.w = fmaf(h0.w, d0, sum.w);
    }
    float di = __ldg(&dinv[node]);
    float di2 = di * di;
    float4 self = __ldg(&X4[(size_t)node * NV + g]);
    float4 z;
    z.x = fmaf(sum.x, di, self.x * di2);
    z.y = fmaf(sum.y, di, self.y * di2);
    z.z = fmaf(sum.z, di, self.z * di2);
    z.w = fmaf(sum.w, di, self.w * di2);
    Z[(size_t)node * NV + g] = z;
}

// ---------------------------------------------------------------------------
// CSR gather-aggregate (agg-after layers):
//   AGG[node] += (sum over incoming src of Hs[src]) * dinv[node]
// AGG pre-holds self-loop + bias. One thread per (node, feature group).
// ---------------------------------------------------------------------------
template <int NV>  // NV = DIM/4
__global__ void agg_csr_v4(const float4* __restrict__ Hs,
                           const int* __restrict__ off,
                           const int* __restrict__ csrc,
                           const float* __restrict__ dinv,
                           float4* __restrict__ AGG, int n) {
    int idx = blockIdx.x * blockDim.x + threadIdx.x;
    if (idx >= n * NV) return;
    int node = idx / NV;
    int g = idx - node * NV;
    int e = __ldg(&off[node]);
    int e1 = __ldg(&off[node + 1]);
    float4 sum = make_float4(0.f, 0.f, 0.f, 0.f);
    for (; e + 3 < e1; e += 4) {
        int s0 = __ldg(&csrc[e]);
        int s1 = __ldg(&csrc[e + 1]);
        int s2 = __ldg(&csrc[e + 2]);
        int s3 = __ldg(&csrc[e + 3]);
        float4 h0 = __ldg(&Hs[(size_t)s0 * NV + g]);
        float4 h1 = __ldg(&Hs[(size_t)s1 * NV + g]);
        float4 h2 = __ldg(&Hs[(size_t)s2 * NV + g]);
        float4 h3 = __ldg(&Hs[(size_t)s3 * NV + g]);
        sum.x += (h0.x + h1.x) + (h2.x + h3.x);
        sum.y += (h0.y + h1.y) + (h2.y + h3.y);
        sum.z += (h0.z + h1.z) + (h2.z + h3.z);
        sum.w += (h0.w + h1.w) + (h2.w + h3.w);
    }
    for (; e < e1; e++) {
        int s0 = __ldg(&csrc[e]);
        float4 h0 = __ldg(&Hs[(size_t)s0 * NV + g]);
        sum.x += h0.x; sum.y += h0.y; sum.z += h0.z; sum.w += h0.w;
    }
    float nd = __ldg(&dinv[node]);
    float4 acc = AGG[(size_t)node * NV + g];
    acc.x = fmaf(sum.x, nd, acc.x);
    acc.y = fmaf(sum.y, nd, acc.y);
    acc.z = fmaf(sum.z, nd, acc.z);
    acc.w = fmaf(sum.w, nd, acc.w);
    AGG[(size_t)node * NV + g] = acc;
}

template <int NV>  // NV = DIM/2 (8B-aligned rows, dim 50)
__global__ void agg_csr_v2(const float2* __restrict__ Hs,
                           const int* __restrict__ off,
                           const int* __restrict__ csrc,
                           const float* __restrict__ dinv,
                           float2* __restrict__ AGG, int n) {
    int idx = blockIdx.x * blockDim.x + threadIdx.x;
    if (idx >= n * NV) return;
    int node = idx / NV;
    int g = idx - node * NV;
    int e = __ldg(&off[node]);
    int e1 = __ldg(&off[node + 1]);
    float2 sum = make_float2(0.f, 0.f);
    for (; e + 3 < e1; e += 4) {
        int s0 = __ldg(&csrc[e]);
        int s1 = __ldg(&csrc[e + 1]);
        int s2 = __ldg(&csrc[e + 2]);
        int s3 = __ldg(&csrc[e + 3]);
        float2 h0 = __ldg(&Hs[(size_t)s0 * NV + g]);
        float2 h1 = __ldg(&Hs[(size_t)s1 * NV + g]);
        float2 h2 = __ldg(&Hs[(size_t)s2 * NV + g]);
        float2 h3 = __ldg(&Hs[(size_t)s3 * NV + g]);
        sum.x += (h0.x + h1.x) + (h2.x + h3.x);
        sum.y += (h0.y + h1.y) + (h2.y + h3.y);
    }
    for (; e < e1; e++) {
        int s0 = __ldg(&csrc[e]);
        float2 h0 = __ldg(&Hs[(size_t)s0 * NV + g]);
        sum.x += h0.x; sum.y += h0.y;
    }
    float nd = __ldg(&dinv[node]);
    float2 acc = AGG[(size_t)node * NV + g];
    acc.x = fmaf(sum.x, nd, acc.x);
    acc.y = fmaf(sum.y, nd, acc.y);
    AGG[(size_t)node * NV + g] = acc;
}

// ---------------------------------------------------------------------------
// Register-tiled fused GEMM.
//   acc = leaky?(X[rows]) @ W       TM x TN tile per thread, f32x2 FMAs
// GCNEPI=true:  Hs = acc*dinv, AGG = acc*dinv^2 + b   (agg-after layers)
// GCNEPI=false: OUT(=AGG param) = acc + b             (plain)
// X and outputs must not alias.
// ---------------------------------------------------------------------------
template <int K, int DOUT, int BM, int BK, int TM, int TN, int THREADS,
          bool LEAKY, bool GCNEPI>
__global__ __launch_bounds__(THREADS)
void gemm_fused(const float* __restrict__ X,
                const float* __restrict__ W,
                const float* __restrict__ b,
                const float* __restrict__ dinv,
                float* __restrict__ Hs,
                float* __restrict__ AGG, int n) {
    constexpr int COLG = DOUT / TN;
    constexpr int ROWG = THREADS / COLG;
    constexpr int NP = TN / 2;
    static_assert(COLG * TN == DOUT, "tn");
    static_assert(COLG * ROWG == THREADS, "thr");
    static_assert(ROWG * TM == BM, "bm");
    static_assert(K % BK == 0, "bk");

    __shared__ __align__(16) float Ws[K * DOUT];
    __shared__ __align__(16) float Xs[BM * (BK + 1)];

    const int tid = threadIdx.x;
    const int row0 = blockIdx.x * BM;
    const int nrows = min(BM, n - row0);

    for (int i = tid; i < K * DOUT; i += THREADS) Ws[i] = W[i];

    const int colg = tid % COLG;
    const int rowg = tid / COLG;
    const int col0 = colg * TN;
    const int r0 = rowg * TM;

    unsigned long long acc[TM][NP];
#pragma unroll
    for (int i = 0; i < TM; i++)
#pragma unroll
        for (int jp = 0; jp < NP; jp++) acc[i][jp] = 0ULL;

    for (int k0 = 0; k0 < K; k0 += BK) {
        __syncthreads();
        for (int i = tid; i < nrows * BK; i += THREADS) {
            int r = i / BK, c = i - r * BK;
            float v = __ldg(&X[(size_t)(row0 + r) * K + k0 + c]);
            if (LEAKY) v = (v > 0.0f) ? v : 0.01f * v;
            Xs[r * (BK + 1) + c] = v;
        }
        __syncthreads();

#pragma unroll 4
        for (int k = 0; k < BK; k++) {
            unsigned long long wv[NP];
            const unsigned long long* wr =
                (const unsigned long long*)&Ws[(k0 + k) * DOUT + col0];
#pragma unroll
            for (int jp = 0; jp < NP; jp++) wv[jp] = wr[jp];
#pragma unroll
            for (int i = 0; i < TM; i++) {
                float xv = Xs[(r0 + i) * (BK + 1) + k];
                unsigned long long xp;
                asm("mov.b64 %0, {%1, %1};" : "=l"(xp) : "f"(xv));
#pragma unroll
                for (int jp = 0; jp < NP; jp++) {
                    asm("fma.rn.f32x2 %0, %1, %2, %0;"
                        : "+l"(acc[i][jp]) : "l"(xp), "l"(wv[jp]));
                }
            }
        }
    }

#pragma unroll
    for (int i = 0; i < TM; i++) {
        int row = row0 + r0 + i;
        if (row >= n) break;
        if (GCNEPI) {
            float di = dinv[row];
            float di2 = di * di;
            float2* hsr = (float2*)(Hs + (size_t)row * DOUT + col0);
            float2* agr = (float2*)(AGG + (size_t)row * DOUT + col0);
#pragma unroll
            for (int jp = 0; jp < NP; jp++) {
                float lo, hi;
                asm("mov.b64 {%0, %1}, %2;" : "=f"(lo), "=f"(hi) : "l"(acc[i][jp]));
                float blo = __ldg(&b[col0 + 2 * jp]);
                float bhi = __ldg(&b[col0 + 2 * jp + 1]);
                hsr[jp] = make_float2(lo * di, hi * di);
                agr[jp] = make_float2(lo * di2 + blo, hi * di2 + bhi);
            }
        } else {
            float2* outr = (float2*)(AGG + (size_t)row * DOUT + col0);
#pragma unroll
            for (int jp = 0; jp < NP; jp++) {
                float lo, hi;
                asm("mov.b64 {%0, %1}, %2;" : "=f"(lo), "=f"(hi) : "l"(acc[i][jp]));
                float blo = __ldg(&b[col0 + 2 * jp]);
                float bhi = __ldg(&b[col0 + 2 * jp + 1]);
                outr[jp] = make_float2(lo + blo, hi + bhi);
            }
        }
    }
}

// ---------------------------------------------------------------------------
// final: logits = leaky(H3) @ Wl + bl, then log_softmax over 10 classes
// ---------------------------------------------------------------------------
__global__ void final_kernel(const float* __restrict__ H,
                             const float* __restrict__ Wl,
                             const float* __restrict__ bl,
                             float* __restrict__ out, int n) {
    __shared__ float Ws[50 * 10];
    __shared__ float bs[10];
    for (int i = threadIdx.x; i < 500; i += blockDim.x) Ws[i] = Wl[i];
    if (threadIdx.x < 10) bs[threadIdx.x] = bl[threadIdx.x];
    __syncthreads();

    int i = blockIdx.x * blockDim.x + threadIdx.x;
    if (i >= n) return;

    float logits[10];
#pragma unroll
    for (int j = 0; j < 10; j++) logits[j] = bs[j];

    const float* hr = H + (size_t)i * 50;
#pragma unroll
    for (int k = 0; k < 50; k++) {
        float v = __ldg(&hr[k]);
        v = (v > 0.0f) ? v : 0.01f * v;
#pragma unroll
        for (int j = 0; j < 10; j++) logits[j] = fmaf(v, Ws[k * 10 + j], logits[j]);
    }

    float mx = logits[0];
#pragma unroll
    for (int j = 1; j < 10; j++) mx = fmaxf(mx, logits[j]);
    float s = 0.0f;
#pragma unroll
    for (int j = 0; j < 10; j++) s += __expf(logits[j] - mx);
    float lse = mx + __logf(s);
#pragma unroll
    for (int j = 0; j < 10; j++) out[(size_t)i * 10 + j] = logits[j] - lse;
}

// ---------------------------------------------------------------------------
// launch
// ---------------------------------------------------------------------------
extern "C" void kernel_launch(void* const* d_in, const int* in_sizes, int n_in,
                              void* d_out, int out_size) {
    const float* x = (const float*)d_in[0];
    const int* edge = (const int*)d_in[1];  // int32 (JAX downcast)
    const float* W1 = (const float*)d_in[2];
    const float* b1 = (const float*)d_in[3];
    const float* W2 = (const float*)d_in[4];
    const float* b2 = (const float*)d_in[5];
    const float* W3 = (const float*)d_in[6];
    const float* b3 = (const float*)d_in[7];
    const float* Wl = (const float*)d_in[8];
    const float* bl = (const float*)d_in[9];
    float* out = (float*)d_out;

    const int n = in_sizes[0] / 64;  // 100000
    const int E = in_sizes[1] / 2;   // 1000000
    const int* src = edge;
    const int* dst = edge + E;

    float *bufA, *bufB, *bufC, *dinv;
    int *deg, *incl, *bsum, *off, *cur, *csrc;
    cudaGetSymbolAddress((void**)&bufA, g_bufA);
    cudaGetSymbolAddress((void**)&bufB, g_bufB);
    cudaGetSymbolAddress((void**)&bufC, g_bufC);
    cudaGetSymbolAddress((void**)&dinv, g_dinv);
    cudaGetSymbolAddress((void**)&deg, g_deg);
    cudaGetSymbolAddress((void**)&incl, g_incl);
    cudaGetSymbolAddress((void**)&bsum, g_bsum);
    cudaGetSymbolAddress((void**)&off, g_off);
    cudaGetSymbolAddress((void**)&cur, g_cur);
    cudaGetSymbolAddress((void**)&csrc, g_csrc);

    const int T = 256;
    const int nb = cdiv(n, SCAN_B);

    // ---- CSR build (by dst) + dinv ----
    deg_zero<<<cdiv(n, T), T>>>(deg, n);
    deg_hist<<<cdiv(E, T), T>>>(dst, deg, E);
    scan_block<<<nb, SCAN_B>>>(deg, incl, bsum, dinv, n);
    finish_offsets<<<cdiv(n, 256), 256>>>(deg, incl, bsum, off, cur, n, E);
    csr_scatter<<<cdiv(E, T), T>>>(src, dst, cur, csrc, E);

    // ---- layer 1: aggregate-first on x (dim 64), then GEMM 64->80 ----
    agg_x_v4<<<cdiv(n * 16, T), T>>>((const float4*)x, off, csrc, dinv,
                                     (float4*)bufB, n);
    gemm_fused<64, 80, 128, 32, 4, 10, 256, false, false>
        <<<cdiv(n, 128), 256>>>(bufB, W1, b1, dinv, bufA, bufC, n);

    // ---- layer 2: 80 -> 40, agg-after ----  X=bufC(leaky), Hs=bufA, AGG=bufB
    gemm_fused<80, 40, 256, 20, 4, 10, 256, true, true>
        <<<cdiv(n, 256), 256>>>(bufC, W2, b2, dinv, bufA, bufB, n);
    agg_csr_v4<10><<<cdiv(n * 10, T), T>>>((const float4*)bufA, off, csrc, dinv,
                                           (float4*)bufB, n);

    // ---- layer 3: 40 -> 50, agg-after ----  X=bufB(leaky), Hs=bufA, AGG=bufC
    gemm_fused<40, 50, 256, 20, 4, 10, 320, true, true>
        <<<cdiv(n, 256), 320>>>(bufB, W3, b3, dinv, bufA, bufC, n);
    agg_csr_v2<25><<<cdiv(n * 25, T), T>>>((const float2*)bufA, off, csrc, dinv,
                                           (float2*)bufC, n);

    // ---- final linear + log_softmax ----
    final_kernel<<<cdiv(n, T), T>>>(bufC, Wl, bl, out, n);
}

// round 10
// speedup vs baseline: 1.3537x; 1.1813x over previous
#include <cuda_runtime.h>
#include <math.h>

// ---------------------------------------------------------------------------
// GCNClassifier: 3x GCNConv (+leaky relu) + linear + log_softmax
// N = 100000, E = 1000000, dims 64 -> 80 -> 40 -> 50 -> 10
// Strategy: per-call CSR build (by dst), thread-per-(node,group) vectorized
// gather aggregation (no float atomics), register-tiled fused GEMMs with
// f32x2 FMAs. Layers 1 and 3 aggregate BEFORE their GEMM (Â(XW) = (ÂX)W);
// the classifier head is fused into gemm3's epilogue.
// ---------------------------------------------------------------------------

#define N_NODES 100000
#define E_MAX   1000000
#define MAX_DIM 80
#define SCAN_B  1024
#define NB_MAX  128   // cdiv(100000,1024)=98

__device__ float g_bufA[N_NODES * MAX_DIM];
__device__ float g_bufB[N_NODES * MAX_DIM];
__device__ float g_bufC[N_NODES * MAX_DIM];
__device__ float g_dinv[N_NODES];
__device__ int   g_deg[N_NODES];
__device__ int   g_incl[N_NODES];
__device__ int   g_bsum[NB_MAX];
__device__ int   g_boff[NB_MAX];
__device__ int   g_off[N_NODES + 1];
__device__ int   g_cur[N_NODES];
__device__ int   g_csrc[E_MAX];

static inline int cdiv(int a, int b) { return (a + b - 1) / b; }

// ---------------------------------------------------------------------------
// CSR build: histogram -> scan -> scatter      (+ dinv = rsqrt(deg+1))
// (exact Round-7 structure — verified fastest)
// ---------------------------------------------------------------------------
__global__ void deg_zero(int* deg, int n) {
    int i = blockIdx.x * blockDim.x + threadIdx.x;
    if (i < n) deg[i] = 0;
}

__global__ void deg_hist(const int* __restrict__ dst, int* deg, int E) {
    int e = blockIdx.x * blockDim.x + threadIdx.x;
    if (e < E) atomicAdd(&deg[__ldg(&dst[e])], 1);
}

__global__ void scan_block(const int* __restrict__ deg, int* incl, int* bsum, int n) {
    __shared__ int sh[SCAN_B];
    int i = blockIdx.x * SCAN_B + threadIdx.x;
    sh[threadIdx.x] = (i < n) ? deg[i] : 0;
    __syncthreads();
#pragma unroll
    for (int ofs = 1; ofs < SCAN_B; ofs <<= 1) {
        int t = (threadIdx.x >= ofs) ? sh[threadIdx.x - ofs] : 0;
        __syncthreads();
        sh[threadIdx.x] += t;
        __syncthreads();
    }
    if (i < n) incl[i] = sh[threadIdx.x];
    if (threadIdx.x == SCAN_B - 1) bsum[blockIdx.x] = sh[SCAN_B - 1];
}

__global__ void scan_bsums(const int* __restrict__ bsum, int* boff, int nb) {
    __shared__ int sh[128];
    int t = threadIdx.x;
    int v = (t < nb) ? bsum[t] : 0;
    sh[t] = v;
    __syncthreads();
#pragma unroll
    for (int ofs = 1; ofs < 128; ofs <<= 1) {
        int u = (t >= ofs) ? sh[t - ofs] : 0;
        __syncthreads();
        sh[t] += u;
        __syncthreads();
    }
    if (t < nb) boff[t] = sh[t] - v;  // exclusive
}

__global__ void finish_offsets(const int* __restrict__ deg,
                               const int* __restrict__ incl,
                               const int* __restrict__ boff,
                               int* off, int* cur, float* dinv, int n, int E) {
    int i = blockIdx.x * blockDim.x + threadIdx.x;
    if (i < n) {
        int o = incl[i] - deg[i] + boff[i >> 10];
        off[i] = o;
        cur[i] = o;
        dinv[i] = rsqrtf((float)deg[i] + 1.0f);
        if (i == 0) off[n] = E;
    }
}

__global__ void csr_scatter(const int* __restrict__ src,
                            const int* __restrict__ dst,
                            int* cur, int* csrc, int E) {
    int e = blockIdx.x * blockDim.x + threadIdx.x;
    if (e < E) {
        int d = __ldg(&dst[e]);
        int pos = atomicAdd(&cur[d], 1);
        csrc[pos] = __ldg(&src[e]);
    }
}

// ---------------------------------------------------------------------------
// Aggregate-first gather (layers 1 and 3):
//   Z[i] = dinv[i] * (sum_s dinv[s]*act(X[s])) + dinv[i]^2 * act(X[i])
// act = leaky_relu(0.01) if LEAKY. One thread per (node, float4 group).
// ---------------------------------------------------------------------------
__device__ __forceinline__ float4 leaky4(float4 v) {
    v.x = (v.x > 0.f) ? v.x : 0.01f * v.x;
    v.y = (v.y > 0.f) ? v.y : 0.01f * v.y;
    v.z = (v.z > 0.f) ? v.z : 0.01f * v.z;
    v.w = (v.w > 0.f) ? v.w : 0.01f * v.w;
    return v;
}

template <int NV, bool LEAKY>
__global__ void agg_pre(const float4* __restrict__ X4,
                        const int* __restrict__ off,
                        const int* __restrict__ csrc,
                        const float* __restrict__ dinv,
                        float4* __restrict__ Z, int n) {
    int idx = blockIdx.x * blockDim.x + threadIdx.x;
    if (idx >= n * NV) return;
    int node = idx / NV;
    int g = idx - node * NV;
    int e = __ldg(&off[node]);
    int e1 = __ldg(&off[node + 1]);
    float4 sum = make_float4(0.f, 0.f, 0.f, 0.f);
    for (; e + 1 < e1; e += 2) {
        int s0 = __ldg(&csrc[e]);
        int s1 = __ldg(&csrc[e + 1]);
        float d0 = __ldg(&dinv[s0]);
        float d1 = __ldg(&dinv[s1]);
        float4 h0 = __ldg(&X4[(size_t)s0 * NV + g]);
        float4 h1 = __ldg(&X4[(size_t)s1 * NV + g]);
        if (LEAKY) { h0 = leaky4(h0); h1 = leaky4(h1); }
        sum.x = fmaf(h0.x, d0, fmaf(h1.x, d1, sum.x));
        sum.y = fmaf(h0.y, d0, fmaf(h1.y, d1, sum.y));
        sum.z = fmaf(h0.z, d0, fmaf(h1.z, d1, sum.z));
        sum.w = fmaf(h0.w, d0, fmaf(h1.w, d1, sum.w));
    }
    if (e < e1) {
        int s0 = __ldg(&csrc[e]);
        float d0 = __ldg(&dinv[s0]);
        float4 h0 = __ldg(&X4[(size_t)s0 * NV + g]);
        if (LEAKY) h0 = leaky4(h0);
        sum.x = fmaf(h0.x, d0, sum.x);
        sum.y = fmaf(h0.y, d0, sum.y);
        sum.z = fmaf(h0.z, d0, sum.z);
        sum.w = fmaf(h0.w, d0, sum.w);
    }
    float di = __ldg(&dinv[node]);
    float di2 = di * di;
    float4 self = __ldg(&X4[(size_t)node * NV + g]);
    if (LEAKY) self = leaky4(self);
    float4 z;
    z.x = fmaf(sum.x, di, self.x * di2);
    z.y = fmaf(sum.y, di, self.y * di2);
    z.z = fmaf(sum.z, di, self.z * di2);
    z.w = fmaf(sum.w, di, self.w * di2);
    Z[(size_t)node * NV + g] = z;
}

// ---------------------------------------------------------------------------
// CSR gather-aggregate (agg-after, layer 2):
//   AGG[node] += (sum over incoming src of Hs[src]) * dinv[node]
// AGG pre-holds self-loop + bias. One thread per (node, feature group).
// ---------------------------------------------------------------------------
template <int NV>  // NV = DIM/4
__global__ void agg_csr_v4(const float4* __restrict__ Hs,
                           const int* __restrict__ off,
                           const int* __restrict__ csrc,
                           const float* __restrict__ dinv,
                           float4* __restrict__ AGG, int n) {
    int idx = blockIdx.x * blockDim.x + threadIdx.x;
    if (idx >= n * NV) return;
    int node = idx / NV;
    int g = idx - node * NV;
    int e = __ldg(&off[node]);
    int e1 = __ldg(&off[node + 1]);
    float4 sum = make_float4(0.f, 0.f, 0.f, 0.f);
    for (; e + 1 < e1; e += 2) {
        int s0 = __ldg(&csrc[e]);
        int s1 = __ldg(&csrc[e + 1]);
        float4 h0 = __ldg(&Hs[(size_t)s0 * NV + g]);
        float4 h1 = __ldg(&Hs[(size_t)s1 * NV + g]);
        sum.x += h0.x + h1.x; sum.y += h0.y + h1.y;
        sum.z += h0.z + h1.z; sum.w += h0.w + h1.w;
    }
    if (e < e1) {
        int s0 = __ldg(&csrc[e]);
        float4 h0 = __ldg(&Hs[(size_t)s0 * NV + g]);
        sum.x += h0.x; sum.y += h0.y; sum.z += h0.z; sum.w += h0.w;
    }
    float nd = __ldg(&dinv[node]);
    float4 acc = AGG[(size_t)node * NV + g];
    acc.x = fmaf(sum.x, nd, acc.x);
    acc.y = fmaf(sum.y, nd, acc.y);
    acc.z = fmaf(sum.z, nd, acc.z);
    acc.w = fmaf(sum.w, nd, acc.w);
    AGG[(size_t)node * NV + g] = acc;
}

// ---------------------------------------------------------------------------
// Register-tiled fused GEMM (layers 1 & 2).
//   acc = leaky?(X[rows]) @ W       TM x TN tile per thread, f32x2 FMAs
// GCNEPI=true:  Hs = acc*dinv, AGG = acc*dinv^2 + b   (agg-after layers)
// GCNEPI=false: OUT(=AGG param) = acc + b             (plain)
// ---------------------------------------------------------------------------
template <int K, int DOUT, int BM, int BK, int TM, int TN, int THREADS,
          bool LEAKY, bool GCNEPI>
__global__ __launch_bounds__(THREADS)
void gemm_fused(const float* __restrict__ X,
                const float* __restrict__ W,
                const float* __restrict__ b,
                const float* __restrict__ dinv,
                float* __restrict__ Hs,
                float* __restrict__ AGG, int n) {
    constexpr int COLG = DOUT / TN;
    constexpr int ROWG = THREADS / COLG;
    constexpr int NP = TN / 2;
    static_assert(COLG * TN == DOUT, "tn");
    static_assert(COLG * ROWG == THREADS, "thr");
    static_assert(ROWG * TM == BM, "bm");
    static_assert(K % BK == 0, "bk");

    __shared__ __align__(16) float Ws[K * DOUT];
    __shared__ __align__(16) float Xs[BM * (BK + 1)];

    const int tid = threadIdx.x;
    const int row0 = blockIdx.x * BM;
    const int nrows = min(BM, n - row0);

    for (int i = tid; i < K * DOUT; i += THREADS) Ws[i] = W[i];

    const int colg = tid % COLG;
    const int rowg = tid / COLG;
    const int col0 = colg * TN;
    const int r0 = rowg * TM;

    unsigned long long acc[TM][NP];
#pragma unroll
    for (int i = 0; i < TM; i++)
#pragma unroll
        for (int jp = 0; jp < NP; jp++) acc[i][jp] = 0ULL;

    for (int k0 = 0; k0 < K; k0 += BK) {
        __syncthreads();
        for (int i = tid; i < nrows * BK; i += THREADS) {
            int r = i / BK, c = i - r * BK;
            float v = __ldg(&X[(size_t)(row0 + r) * K + k0 + c]);
            if (LEAKY) v = (v > 0.0f) ? v : 0.01f * v;
            Xs[r * (BK + 1) + c] = v;
        }
        __syncthreads();

#pragma unroll 4
        for (int k = 0; k < BK; k++) {
            unsigned long long wv[NP];
            const unsigned long long* wr =
                (const unsigned long long*)&Ws[(k0 + k) * DOUT + col0];
#pragma unroll
            for (int jp = 0; jp < NP; jp++) wv[jp] = wr[jp];
#pragma unroll
            for (int i = 0; i < TM; i++) {
                float xv = Xs[(r0 + i) * (BK + 1) + k];
                unsigned long long xp;
                asm("mov.b64 %0, {%1, %1};" : "=l"(xp) : "f"(xv));
#pragma unroll
                for (int jp = 0; jp < NP; jp++) {
                    asm("fma.rn.f32x2 %0, %1, %2, %0;"
                        : "+l"(acc[i][jp]) : "l"(xp), "l"(wv[jp]));
                }
            }
        }
    }

#pragma unroll
    for (int i = 0; i < TM; i++) {
        int row = row0 + r0 + i;
        if (row >= n) break;
        if (GCNEPI) {
            float di = dinv[row];
            float di2 = di * di;
            float2* hsr = (float2*)(Hs + (size_t)row * DOUT + col0);
            float2* agr = (float2*)(AGG + (size_t)row * DOUT + col0);
#pragma unroll
            for (int jp = 0; jp < NP; jp++) {
                float lo, hi;
                asm("mov.b64 {%0, %1}, %2;" : "=f"(lo), "=f"(hi) : "l"(acc[i][jp]));
                float blo = __ldg(&b[col0 + 2 * jp]);
                float bhi = __ldg(&b[col0 + 2 * jp + 1]);
                hsr[jp] = make_float2(lo * di, hi * di);
                agr[jp] = make_float2(lo * di2 + blo, hi * di2 + bhi);
            }
        } else {
            float2* outr = (float2*)(AGG + (size_t)row * DOUT + col0);
#pragma unroll
            for (int jp = 0; jp < NP; jp++) {
                float lo, hi;
                asm("mov.b64 {%0, %1}, %2;" : "=f"(lo), "=f"(hi) : "l"(acc[i][jp]));
                float blo = __ldg(&b[col0 + 2 * jp]);
                float bhi = __ldg(&b[col0 + 2 * jp + 1]);
                outr[jp] = make_float2(lo + blo, hi + bhi);
            }
        }
    }
}

// ---------------------------------------------------------------------------
// gemm3 + classifier head, fused.
//   H3 = Z3 @ W3 + b3   (Z3 already aggregated -> H3 is the layer-3 output)
//   v = leaky(H3); logits = v @ Wl + bl; out = log_softmax(logits)
// Tile staged in padded smem (stride 53 -> conflict-free head reads).
// K=40, DOUT=50, BM=128, BK=20, TM=4, TN=10, THREADS=160.
// ---------------------------------------------------------------------------
__global__ __launch_bounds__(160)
void gemm3_head(const float* __restrict__ X,
                const float* __restrict__ W,
                const float* __restrict__ b,
                const float* __restrict__ Wl,
                const float* __restrict__ bl,
                float* __restrict__ out, int n) {
    constexpr int K = 40, DOUT = 50, BM = 128, BK = 20;
    constexpr int TM = 4, TN = 10, THREADS = 160, COLG = 5, NP = TN / 2;
    constexpr int VP = DOUT + 3;  // 53: conflict-free row stride

    __shared__ __align__(16) float Ws[K * DOUT];       // 2000
    __shared__ __align__(16) float Xs[BM * (BK + 1)];  // 2688
    __shared__ float Wl_s[500];
    __shared__ float bl_s[10];
    __shared__ float bs[DOUT];
    __shared__ float vrow[BM * VP];                    // 6784

    const int tid = threadIdx.x;
    const int row0 = blockIdx.x * BM;
    const int nrows = min(BM, n - row0);

    for (int i = tid; i < K * DOUT; i += THREADS) Ws[i] = W[i];
    for (int i = tid; i < 500; i += THREADS) Wl_s[i] = Wl[i];
    if (tid < 10) bl_s[tid] = bl[tid];
    if (tid < DOUT) bs[tid] = b[tid];

    const int colg = tid % COLG;
    const int rowg = tid / COLG;
    const int col0 = colg * TN;
    const int r0 = rowg * TM;

    unsigned long long acc[TM][NP];
#pragma unroll
    for (int i = 0; i < TM; i++)
#pragma unroll
        for (int jp = 0; jp < NP; jp++) acc[i][jp] = 0ULL;

    for (int k0 = 0; k0 < K; k0 += BK) {
        __syncthreads();
        for (int i = tid; i < nrows * BK; i += THREADS) {
            int r = i / BK, c = i - r * BK;
            Xs[r * (BK + 1) + c] = __ldg(&X[(size_t)(row0 + r) * K + k0 + c]);
        }
        __syncthreads();

#pragma unroll 4
        for (int k = 0; k < BK; k++) {
            unsigned long long wv[NP];
            const unsigned long long* wr =
                (const unsigned long long*)&Ws[(k0 + k) * DOUT + col0];
#pragma unroll
            for (int jp = 0; jp < NP; jp++) wv[jp] = wr[jp];
#pragma unroll
            for (int i = 0; i < TM; i++) {
                float xv = Xs[(r0 + i) * (BK + 1) + k];
                unsigned long long xp;
                asm("mov.b64 %0, {%1, %1};" : "=l"(xp) : "f"(xv));
#pragma unroll
                for (int jp = 0; jp < NP; jp++) {
                    asm("fma.rn.f32x2 %0, %1, %2, %0;"
                        : "+l"(acc[i][jp]) : "l"(xp), "l"(wv[jp]));
                }
            }
        }
    }

    // stage leaky(h3) tile into smem
#pragma unroll
    for (int i = 0; i < TM; i++) {
        int r = r0 + i;
#pragma unroll
        for (int jp = 0; jp < NP; jp++) {
            float lo, hi;
            asm("mov.b64 {%0, %1}, %2;" : "=f"(lo), "=f"(hi) : "l"(acc[i][jp]));
            lo += bs[col0 + 2 * jp];
            hi += bs[col0 + 2 * jp + 1];
            lo = (lo > 0.f) ? lo : 0.01f * lo;
            hi = (hi > 0.f) ? hi : 0.01f * hi;
            vrow[r * VP + col0 + 2 * jp] = lo;
            vrow[r * VP + col0 + 2 * jp + 1] = hi;
        }
    }
    __syncthreads();

    // head: one thread per row
    if (tid < nrows) {
        const float* vr = &vrow[tid * VP];
        float logits[10];
#pragma unroll
        for (int j = 0; j < 10; j++) logits[j] = bl_s[j];
#pragma unroll
        for (int k = 0; k < DOUT; k++) {
            float v = vr[k];
#pragma unroll
            for (int j = 0; j < 10; j++)
                logits[j] = fmaf(v, Wl_s[k * 10 + j], logits[j]);
        }
        float mx = logits[0];
#pragma unroll
        for (int j = 1; j < 10; j++) mx = fmaxf(mx, logits[j]);
        float s = 0.f;
#pragma unroll
        for (int j = 0; j < 10; j++) s += __expf(logits[j] - mx);
        float lse = mx + __logf(s);
        float* outr = out + (size_t)(row0 + tid) * 10;
#pragma unroll
        for (int j = 0; j < 10; j++) outr[j] = logits[j] - lse;
    }
}

// ---------------------------------------------------------------------------
// launch
// ---------------------------------------------------------------------------
extern "C" void kernel_launch(void* const* d_in, const int* in_sizes, int n_in,
                              void* d_out, int out_size) {
    const float* x = (const float*)d_in[0];
    const int* edge = (const int*)d_in[1];  // int32 (JAX downcast)
    const float* W1 = (const float*)d_in[2];
    const float* b1 = (const float*)d_in[3];
    const float* W2 = (const float*)d_in[4];
    const float* b2 = (const float*)d_in[5];
    const float* W3 = (const float*)d_in[6];
    const float* b3 = (const float*)d_in[7];
    const float* Wl = (const float*)d_in[8];
    const float* bl = (const float*)d_in[9];
    float* out = (float*)d_out;

    const int n = in_sizes[0] / 64;  // 100000
    const int E = in_sizes[1] / 2;   // 1000000
    const int* src = edge;
    const int* dst = edge + E;

    float *bufA, *bufB, *bufC, *dinv;
    int *deg, *incl, *bsum, *boff, *off, *cur, *csrc;
    cudaGetSymbolAddress((void**)&bufA, g_bufA);
    cudaGetSymbolAddress((void**)&bufB, g_bufB);
    cudaGetSymbolAddress((void**)&bufC, g_bufC);
    cudaGetSymbolAddress((void**)&dinv, g_dinv);
    cudaGetSymbolAddress((void**)&deg, g_deg);
    cudaGetSymbolAddress((void**)&incl, g_incl);
    cudaGetSymbolAddress((void**)&bsum, g_bsum);
    cudaGetSymbolAddress((void**)&boff, g_boff);
    cudaGetSymbolAddress((void**)&off, g_off);
    cudaGetSymbolAddress((void**)&cur, g_cur);
    cudaGetSymbolAddress((void**)&csrc, g_csrc);

    const int T = 256;
    const int nb = cdiv(n, SCAN_B);

    // ---- CSR build (by dst) + dinv ----
    deg_zero<<<cdiv(n, T), T>>>(deg, n);
    deg_hist<<<cdiv(E, T), T>>>(dst, deg, E);
    scan_block<<<nb, SCAN_B>>>(deg, incl, bsum, n);
    scan_bsums<<<1, 128>>>(bsum, boff, nb);
    finish_offsets<<<cdiv(n, T), T>>>(deg, incl, boff, off, cur, dinv, n, E);
    csr_scatter<<<cdiv(E, T), T>>>(src, dst, cur, csrc, E);

    // ---- layer 1: aggregate-first on x (dim 64), then GEMM 64->80 ----
    agg_pre<16, false><<<cdiv(n * 16, T), T>>>((const float4*)x, off, csrc,
                                               dinv, (float4*)bufB, n);
    gemm_fused<64, 80, 128, 32, 4, 10, 256, false, false>
        <<<cdiv(n, 128), 256>>>(bufB, W1, b1, dinv, bufA, bufC, n);

    // ---- layer 2: 80 -> 40, agg-after ----  X=bufC(leaky), Hs=bufA, AGG=bufB
    gemm_fused<80, 40, 256, 20, 4, 10, 256, true, true>
        <<<cdiv(n, 256), 256>>>(bufC, W2, b2, dinv, bufA, bufB, n);
    agg_csr_v4<10><<<cdiv(n * 10, T), T>>>((const float4*)bufA, off, csrc, dinv,
                                           (float4*)bufB, n);

    // ---- layer 3: aggregate-first on leaky(A2) (dim 40) ----
    agg_pre<10, true><<<cdiv(n * 10, T), T>>>((const float4*)bufB, off, csrc,
                                              dinv, (float4*)bufC, n);

    // ---- gemm3 (40->50) fused with classifier head + log_softmax ----
    gemm3_head<<<cdiv(n, 128), 160>>>(bufC, W3, b3, Wl, bl, out, n);
}

// round 11
// speedup vs baseline: 1.3797x; 1.0192x over previous
#include <cuda_runtime.h>
#include <math.h>

// ---------------------------------------------------------------------------
// GCNClassifier: 3x GCNConv (+leaky relu) + linear + log_softmax
// N = 100000, E = 1000000, dims 64 -> 80 -> 40 -> 50 -> 10
// Strategy: per-call CSR build (by dst, block-reserved ranges -> 4 launches),
// thread-per-(node,group) vectorized gather aggregation (no float atomics),
// register-tiled fused GEMMs with f32x2 FMAs. Layers 1 and 3 aggregate
// BEFORE their GEMM (Â(XW) = (ÂX)W); classifier head fused into gemm3.
// ---------------------------------------------------------------------------

#define N_NODES 100000
#define E_MAX   1000000
#define MAX_DIM 80
#define SCAN_B  1024

__device__ float g_bufA[N_NODES * MAX_DIM];
__device__ float g_bufB[N_NODES * MAX_DIM];
__device__ float g_bufC[N_NODES * MAX_DIM];
__device__ float g_dinv[N_NODES];
__device__ int   g_deg[N_NODES];
__device__ int   g_off[N_NODES];
__device__ int   g_cur[N_NODES];
__device__ int   g_csrc[E_MAX];
__device__ int   g_counter;

static inline int cdiv(int a, int b) { return (a + b - 1) / b; }

// ---------------------------------------------------------------------------
// CSR build: zero -> histogram -> scan+reserve -> scatter
// Each scan block atomically reserves a contiguous range for its 1024 nodes;
// off[] is NOT monotone in node id, so range end = off[node] + deg[node].
// ---------------------------------------------------------------------------
__global__ void deg_zero(int* deg, int* counter, int n) {
    int i = blockIdx.x * blockDim.x + threadIdx.x;
    if (i < n) deg[i] = 0;
    if (i == 0) *counter = 0;
}

__global__ void deg_hist(const int* __restrict__ dst, int* deg, int E) {
    int e = blockIdx.x * blockDim.x + threadIdx.x;
    if (e < E) atomicAdd(&deg[__ldg(&dst[e])], 1);
}

__global__ void scan_reserve(const int* __restrict__ deg,
                             int* off, int* cur, float* dinv,
                             int* counter, int n) {
    __shared__ int sh[SCAN_B];
    __shared__ int base_sh;
    int i = blockIdx.x * SCAN_B + threadIdx.x;
    int d = (i < n) ? deg[i] : 0;
    sh[threadIdx.x] = d;
    if (i < n) dinv[i] = rsqrtf((float)d + 1.0f);
    __syncthreads();
#pragma unroll
    for (int ofs = 1; ofs < SCAN_B; ofs <<= 1) {
        int t = (threadIdx.x >= ofs) ? sh[threadIdx.x - ofs] : 0;
        __syncthreads();
        sh[threadIdx.x] += t;
        __syncthreads();
    }
    if (threadIdx.x == SCAN_B - 1)
        base_sh = atomicAdd(counter, sh[SCAN_B - 1]);
    __syncthreads();
    if (i < n) {
        int o = base_sh + sh[threadIdx.x] - d;
        off[i] = o;
        cur[i] = o;
    }
}

__global__ void csr_scatter(const int* __restrict__ src,
                            const int* __restrict__ dst,
                            int* cur, int* csrc, int E) {
    int e = blockIdx.x * blockDim.x + threadIdx.x;
    if (e < E) {
        int d = __ldg(&dst[e]);
        int pos = atomicAdd(&cur[d], 1);
        csrc[pos] = __ldg(&src[e]);
    }
}

// ---------------------------------------------------------------------------
// Aggregate-first gather (layers 1 and 3):
//   Z[i] = dinv[i] * (sum_s dinv[s]*act(X[s])) + dinv[i]^2 * act(X[i])
// act = leaky_relu(0.01) if LEAKY. One thread per (node, float4 group).
// ---------------------------------------------------------------------------
__device__ __forceinline__ float4 leaky4(float4 v) {
    v.x = (v.x > 0.f) ? v.x : 0.01f * v.x;
    v.y = (v.y > 0.f) ? v.y : 0.01f * v.y;
    v.z = (v.z > 0.f) ? v.z : 0.01f * v.z;
    v.w = (v.w > 0.f) ? v.w : 0.01f * v.w;
    return v;
}

template <int NV, bool LEAKY>
__global__ void agg_pre(const float4* __restrict__ X4,
                        const int* __restrict__ off,
                        const int* __restrict__ deg,
                        const int* __restrict__ csrc,
                        const float* __restrict__ dinv,
                        float4* __restrict__ Z, int n) {
    int idx = blockIdx.x * blockDim.x + threadIdx.x;
    if (idx >= n * NV) return;
    int node = idx / NV;
    int g = idx - node * NV;
    int e = __ldg(&off[node]);
    int e1 = e + __ldg(&deg[node]);
    float4 sum = make_float4(0.f, 0.f, 0.f, 0.f);
    for (; e + 1 < e1; e += 2) {
        int s0 = __ldg(&csrc[e]);
        int s1 = __ldg(&csrc[e + 1]);
        float d0 = __ldg(&dinv[s0]);
        float d1 = __ldg(&dinv[s1]);
        float4 h0 = __ldg(&X4[(size_t)s0 * NV + g]);
        float4 h1 = __ldg(&X4[(size_t)s1 * NV + g]);
        if (LEAKY) { h0 = leaky4(h0); h1 = leaky4(h1); }
        sum.x = fmaf(h0.x, d0, fmaf(h1.x, d1, sum.x));
        sum.y = fmaf(h0.y, d0, fmaf(h1.y, d1, sum.y));
        sum.z = fmaf(h0.z, d0, fmaf(h1.z, d1, sum.z));
        sum.w = fmaf(h0.w, d0, fmaf(h1.w, d1, sum.w));
    }
    if (e < e1) {
        int s0 = __ldg(&csrc[e]);
        float d0 = __ldg(&dinv[s0]);
        float4 h0 = __ldg(&X4[(size_t)s0 * NV + g]);
        if (LEAKY) h0 = leaky4(h0);
        sum.x = fmaf(h0.x, d0, sum.x);
        sum.y = fmaf(h0.y, d0, sum.y);
        sum.z = fmaf(h0.z, d0, sum.z);
        sum.w = fmaf(h0.w, d0, sum.w);
    }
    float di = __ldg(&dinv[node]);
    float di2 = di * di;
    float4 self = __ldg(&X4[(size_t)node * NV + g]);
    if (LEAKY) self = leaky4(self);
    float4 z;
    z.x = fmaf(sum.x, di, self.x * di2);
    z.y = fmaf(sum.y, di, self.y * di2);
    z.z = fmaf(sum.z, di, self.z * di2);
    z.w = fmaf(sum.w, di, self.w * di2);
    Z[(size_t)node * NV + g] = z;
}

// ---------------------------------------------------------------------------
// CSR gather-aggregate (agg-after, layer 2):
//   AGG[node] += (sum over incoming src of Hs[src]) * dinv[node]
// AGG pre-holds self-loop + bias. One thread per (node, feature group).
// ---------------------------------------------------------------------------
template <int NV>  // NV = DIM/4
__global__ void agg_csr_v4(const float4* __restrict__ Hs,
                           const int* __restrict__ off,
                           const int* __restrict__ deg,
                           const int* __restrict__ csrc,
                           const float* __restrict__ dinv,
                           float4* __restrict__ AGG, int n) {
    int idx = blockIdx.x * blockDim.x + threadIdx.x;
    if (idx >= n * NV) return;
    int node = idx / NV;
    int g = idx - node * NV;
    int e = __ldg(&off[node]);
    int e1 = e + __ldg(&deg[node]);
    float4 sum = make_float4(0.f, 0.f, 0.f, 0.f);
    for (; e + 1 < e1; e += 2) {
        int s0 = __ldg(&csrc[e]);
        int s1 = __ldg(&csrc[e + 1]);
        float4 h0 = __ldg(&Hs[(size_t)s0 * NV + g]);
        float4 h1 = __ldg(&Hs[(size_t)s1 * NV + g]);
        sum.x += h0.x + h1.x; sum.y += h0.y + h1.y;
        sum.z += h0.z + h1.z; sum.w += h0.w + h1.w;
    }
    if (e < e1) {
        int s0 = __ldg(&csrc[e]);
        float4 h0 = __ldg(&Hs[(size_t)s0 * NV + g]);
        sum.x += h0.x; sum.y += h0.y; sum.z += h0.z; sum.w += h0.w;
    }
    float nd = __ldg(&dinv[node]);
    float4 acc = AGG[(size_t)node * NV + g];
    acc.x = fmaf(sum.x, nd, acc.x);
    acc.y = fmaf(sum.y, nd, acc.y);
    acc.z = fmaf(sum.z, nd, acc.z);
    acc.w = fmaf(sum.w, nd, acc.w);
    AGG[(size_t)node * NV + g] = acc;
}

// ---------------------------------------------------------------------------
// Register-tiled fused GEMM (layers 1 & 2).
//   acc = leaky?(X[rows]) @ W       TM x TN tile per thread, f32x2 FMAs
// GCNEPI=true:  Hs = acc*dinv, AGG = acc*dinv^2 + b   (agg-after layers)
// GCNEPI=false: OUT(=AGG param) = acc + b             (plain)
// ---------------------------------------------------------------------------
template <int K, int DOUT, int BM, int BK, int TM, int TN, int THREADS,
          bool LEAKY, bool GCNEPI>
__global__ __launch_bounds__(THREADS)
void gemm_fused(const float* __restrict__ X,
                const float* __restrict__ W,
                const float* __restrict__ b,
                const float* __restrict__ dinv,
                float* __restrict__ Hs,
                float* __restrict__ AGG, int n) {
    constexpr int COLG = DOUT / TN;
    constexpr int ROWG = THREADS / COLG;
    constexpr int NP = TN / 2;
    static_assert(COLG * TN == DOUT, "tn");
    static_assert(COLG * ROWG == THREADS, "thr");
    static_assert(ROWG * TM == BM, "bm");
    static_assert(K % BK == 0, "bk");

    __shared__ __align__(16) float Ws[K * DOUT];
    __shared__ __align__(16) float Xs[BM * (BK + 1)];

    const int tid = threadIdx.x;
    const int row0 = blockIdx.x * BM;
    const int nrows = min(BM, n - row0);

    for (int i = tid; i < K * DOUT; i += THREADS) Ws[i] = W[i];

    const int colg = tid % COLG;
    const int rowg = tid / COLG;
    const int col0 = colg * TN;
    const int r0 = rowg * TM;

    unsigned long long acc[TM][NP];
#pragma unroll
    for (int i = 0; i < TM; i++)
#pragma unroll
        for (int jp = 0; jp < NP; jp++) acc[i][jp] = 0ULL;

    for (int k0 = 0; k0 < K; k0 += BK) {
        __syncthreads();
        for (int i = tid; i < nrows * BK; i += THREADS) {
            int r = i / BK, c = i - r * BK;
            float v = __ldg(&X[(size_t)(row0 + r) * K + k0 + c]);
            if (LEAKY) v = (v > 0.0f) ? v : 0.01f * v;
            Xs[r * (BK + 1) + c] = v;
        }
        __syncthreads();

#pragma unroll 4
        for (int k = 0; k < BK; k++) {
            unsigned long long wv[NP];
            const unsigned long long* wr =
                (const unsigned long long*)&Ws[(k0 + k) * DOUT + col0];
#pragma unroll
            for (int jp = 0; jp < NP; jp++) wv[jp] = wr[jp];
#pragma unroll
            for (int i = 0; i < TM; i++) {
                float xv = Xs[(r0 + i) * (BK + 1) + k];
                unsigned long long xp;
                asm("mov.b64 %0, {%1, %1};" : "=l"(xp) : "f"(xv));
#pragma unroll
                for (int jp = 0; jp < NP; jp++) {
                    asm("fma.rn.f32x2 %0, %1, %2, %0;"
                        : "+l"(acc[i][jp]) : "l"(xp), "l"(wv[jp]));
                }
            }
        }
    }

#pragma unroll
    for (int i = 0; i < TM; i++) {
        int row = row0 + r0 + i;
        if (row >= n) break;
        if (GCNEPI) {
            float di = dinv[row];
            float di2 = di * di;
            float2* hsr = (float2*)(Hs + (size_t)row * DOUT + col0);
            float2* agr = (float2*)(AGG + (size_t)row * DOUT + col0);
#pragma unroll
            for (int jp = 0; jp < NP; jp++) {
                float lo, hi;
                asm("mov.b64 {%0, %1}, %2;" : "=f"(lo), "=f"(hi) : "l"(acc[i][jp]));
                float blo = __ldg(&b[col0 + 2 * jp]);
                float bhi = __ldg(&b[col0 + 2 * jp + 1]);
                hsr[jp] = make_float2(lo * di, hi * di);
                agr[jp] = make_float2(lo * di2 + blo, hi * di2 + bhi);
            }
        } else {
            float2* outr = (float2*)(AGG + (size_t)row * DOUT + col0);
#pragma unroll
            for (int jp = 0; jp < NP; jp++) {
                float lo, hi;
                asm("mov.b64 {%0, %1}, %2;" : "=f"(lo), "=f"(hi) : "l"(acc[i][jp]));
                float blo = __ldg(&b[col0 + 2 * jp]);
                float bhi = __ldg(&b[col0 + 2 * jp + 1]);
                outr[jp] = make_float2(lo + blo, hi + bhi);
            }
        }
    }
}

// ---------------------------------------------------------------------------
// gemm3 + classifier head, fused.
//   H3 = Z3 @ W3 + b3   (Z3 already aggregated -> H3 is the layer-3 output)
//   v = leaky(H3); logits = v @ Wl + bl; out = log_softmax(logits)
// Tile staged in padded smem (stride 53 -> conflict-free head reads).
// K=40, DOUT=50, BM=128, BK=20, TM=4, TN=10, THREADS=160.
// ---------------------------------------------------------------------------
__global__ __launch_bounds__(160)
void gemm3_head(const float* __restrict__ X,
                const float* __restrict__ W,
                const float* __restrict__ b,
                const float* __restrict__ Wl,
                const float* __restrict__ bl,
                float* __restrict__ out, int n) {
    constexpr int K = 40, DOUT = 50, BM = 128, BK = 20;
    constexpr int TM = 4, TN = 10, THREADS = 160, COLG = 5, NP = TN / 2;
    constexpr int VP = DOUT + 3;  // 53: conflict-free row stride

    __shared__ __align__(16) float Ws[K * DOUT];       // 2000
    __shared__ __align__(16) float Xs[BM * (BK + 1)];  // 2688
    __shared__ float Wl_s[500];
    __shared__ float bl_s[10];
    __shared__ float bs[DOUT];
    __shared__ float vrow[BM * VP];                    // 6784

    const int tid = threadIdx.x;
    const int row0 = blockIdx.x * BM;
    const int nrows = min(BM, n - row0);

    for (int i = tid; i < K * DOUT; i += THREADS) Ws[i] = W[i];
    for (int i = tid; i < 500; i += THREADS) Wl_s[i] = Wl[i];
    if (tid < 10) bl_s[tid] = bl[tid];
    if (tid < DOUT) bs[tid] = b[tid];

    const int colg = tid % COLG;
    const int rowg = tid / COLG;
    const int col0 = colg * TN;
    const int r0 = rowg * TM;

    unsigned long long acc[TM][NP];
#pragma unroll
    for (int i = 0; i < TM; i++)
#pragma unroll
        for (int jp = 0; jp < NP; jp++) acc[i][jp] = 0ULL;

    for (int k0 = 0; k0 < K; k0 += BK) {
        __syncthreads();
        for (int i = tid; i < nrows * BK; i += THREADS) {
            int r = i / BK, c = i - r * BK;
            Xs[r * (BK + 1) + c] = __ldg(&X[(size_t)(row0 + r) * K + k0 + c]);
        }
        __syncthreads();

#pragma unroll 4
        for (int k = 0; k < BK; k++) {
            unsigned long long wv[NP];
            const unsigned long long* wr =
                (const unsigned long long*)&Ws[(k0 + k) * DOUT + col0];
#pragma unroll
            for (int jp = 0; jp < NP; jp++) wv[jp] = wr[jp];
#pragma unroll
            for (int i = 0; i < TM; i++) {
                float xv = Xs[(r0 + i) * (BK + 1) + k];
                unsigned long long xp;
                asm("mov.b64 %0, {%1, %1};" : "=l"(xp) : "f"(xv));
#pragma unroll
                for (int jp = 0; jp < NP; jp++) {
                    asm("fma.rn.f32x2 %0, %1, %2, %0;"
                        : "+l"(acc[i][jp]) : "l"(xp), "l"(wv[jp]));
                }
            }
        }
    }

    // stage leaky(h3) tile into smem
#pragma unroll
    for (int i = 0; i < TM; i++) {
        int r = r0 + i;
#pragma unroll
        for (int jp = 0; jp < NP; jp++) {
            float lo, hi;
            asm("mov.b64 {%0, %1}, %2;" : "=f"(lo), "=f"(hi) : "l"(acc[i][jp]));
            lo += bs[col0 + 2 * jp];
            hi += bs[col0 + 2 * jp + 1];
            lo = (lo > 0.f) ? lo : 0.01f * lo;
            hi = (hi > 0.f) ? hi : 0.01f * hi;
            vrow[r * VP + col0 + 2 * jp] = lo;
            vrow[r * VP + col0 + 2 * jp + 1] = hi;
        }
    }
    __syncthreads();

    // head: one thread per row
    if (tid < nrows) {
        const float* vr = &vrow[tid * VP];
        float logits[10];
#pragma unroll
        for (int j = 0; j < 10; j++) logits[j] = bl_s[j];
#pragma unroll
        for (int k = 0; k < DOUT; k++) {
            float v = vr[k];
#pragma unroll
            for (int j = 0; j < 10; j++)
                logits[j] = fmaf(v, Wl_s[k * 10 + j], logits[j]);
        }
        float mx = logits[0];
#pragma unroll
        for (int j = 1; j < 10; j++) mx = fmaxf(mx, logits[j]);
        float s = 0.f;
#pragma unroll
        for (int j = 0; j < 10; j++) s += __expf(logits[j] - mx);
        float lse = mx + __logf(s);
        float* outr = out + (size_t)(row0 + tid) * 10;
#pragma unroll
        for (int j = 0; j < 10; j++) outr[j] = logits[j] - lse;
    }
}

// ---------------------------------------------------------------------------
// launch
// ---------------------------------------------------------------------------
extern "C" void kernel_launch(void* const* d_in, const int* in_sizes, int n_in,
                              void* d_out, int out_size) {
    const float* x = (const float*)d_in[0];
    const int* edge = (const int*)d_in[1];  // int32 (JAX downcast)
    const float* W1 = (const float*)d_in[2];
    const float* b1 = (const float*)d_in[3];
    const float* W2 = (const float*)d_in[4];
    const float* b2 = (const float*)d_in[5];
    const float* W3 = (const float*)d_in[6];
    const float* b3 = (const float*)d_in[7];
    const float* Wl = (const float*)d_in[8];
    const float* bl = (const float*)d_in[9];
    float* out = (float*)d_out;

    const int n = in_sizes[0] / 64;  // 100000
    const int E = in_sizes[1] / 2;   // 1000000
    const int* src = edge;
    const int* dst = edge + E;

    float *bufA, *bufB, *bufC, *dinv;
    int *deg, *off, *cur, *csrc, *counter;
    cudaGetSymbolAddress((void**)&bufA, g_bufA);
    cudaGetSymbolAddress((void**)&bufB, g_bufB);
    cudaGetSymbolAddress((void**)&bufC, g_bufC);
    cudaGetSymbolAddress((void**)&dinv, g_dinv);
    cudaGetSymbolAddress((void**)&deg, g_deg);
    cudaGetSymbolAddress((void**)&off, g_off);
    cudaGetSymbolAddress((void**)&cur, g_cur);
    cudaGetSymbolAddress((void**)&csrc, g_csrc);
    cudaGetSymbolAddress((void**)&counter, g_counter);

    const int T = 256;
    const int nb = cdiv(n, SCAN_B);

    // ---- CSR build (by dst) + dinv : 4 launches ----
    deg_zero<<<cdiv(n, T), T>>>(deg, counter, n);
    deg_hist<<<cdiv(E, T), T>>>(dst, deg, E);
    scan_reserve<<<nb, SCAN_B>>>(deg, off, cur, dinv, counter, n);
    csr_scatter<<<cdiv(E, T), T>>>(src, dst, cur, csrc, E);

    // ---- layer 1: aggregate-first on x (dim 64), then GEMM 64->80 ----
    agg_pre<16, false><<<cdiv(n * 16, T), T>>>((const float4*)x, off, deg,
                                               csrc, dinv, (float4*)bufB, n);
    gemm_fused<64, 80, 128, 32, 4, 10, 256, false, false>
        <<<cdiv(n, 128), 256>>>(bufB, W1, b1, dinv, bufA, bufC, n);

    // ---- layer 2: 80 -> 40, agg-after ----  X=bufC(leaky), Hs=bufA, AGG=bufB
    gemm_fused<80, 40, 256, 20, 4, 10, 256, true, true>
        <<<cdiv(n, 256), 256>>>(bufC, W2, b2, dinv, bufA, bufB, n);
    agg_csr_v4<10><<<cdiv(n * 10, T), T>>>((const float4*)bufA, off, deg, csrc,
                                           dinv, (float4*)bufB, n);

    // ---- layer 3: aggregate-first on leaky(A2) (dim 40) ----
    agg_pre<10, true><<<cdiv(n * 10, T), T>>>((const float4*)bufB, off, deg,
                                              csrc, dinv, (float4*)bufC, n);

    // ---- gemm3 (40->50) fused with classifier head + log_softmax ----
    gemm3_head<<<cdiv(n, 128), 160>>>(bufC, W3, b3, Wl, bl, out, n);
}